// round 1
// baseline (speedup 1.0000x reference)
#include <cuda_runtime.h>

#define TT     2048
#define HID    512
#define EMB    256
#define GATES  2048
#define KTAGS  48
#define START_TAG 45
#define END_TAG   46
#define NEGV  -100000.0f
#define NSCAN  64   // blocks per direction in the recurrent scan

// ---------------- device-global scratch (no allocations allowed) ----------------
__device__ __align__(128) float g_x[TT * EMB];          // embedded tokens      2 MB
__device__ __align__(128) float g_g[2][TT * GATES];     // gate preactivations 32 MB (reused layer0/layer1)
__device__ __align__(128) float g_h0[TT * 1024];        // layer0 output (fwd|bwd) 8 MB
__device__ __align__(128) float g_h1[TT * 1024];        // layer1 output           8 MB
__device__ __align__(128) float g_feats[TT * KTAGS];    // emission scores
__device__ unsigned g_flags[2 * NSCAN];                 // scan barrier flags

__device__ __forceinline__ float fsig(float x) {
    return __fdividef(1.0f, 1.0f + __expf(-x));
}
__device__ __forceinline__ float ftanh(float x) {
    return 2.0f * __fdividef(1.0f, 1.0f + __expf(-2.0f * x)) - 1.0f;
}

// ---------------- init: zero barrier flags (needed every graph replay) ----------
__global__ void init_k() {
    if (threadIdx.x < 2 * NSCAN) g_flags[threadIdx.x] = 0u;
}

// ---------------- embedding gather ----------------------------------------------
__global__ void embed_k(const int* __restrict__ tokens, const float* __restrict__ emb) {
    int t = blockIdx.x;
    int tok = tokens[t];
    const float4* src = (const float4*)(emb + (size_t)tok * EMB);
    float4* dst = (float4*)(g_x + (size_t)t * EMB);
    for (int i = threadIdx.x; i < EMB / 4; i += blockDim.x) dst[i] = src[i];
}

// ---------------- fp32 GEMM (NT): C[t,n] = sum_k A[t,k]*B[n,k] + b1[n]+b2[n] -----
// A = g_x (srcSel=0, K=256) or g_h0 (srcSel=1, K=1024); C = g_g[slot]; M=TT,N=GATES
__global__ __launch_bounds__(256) void gemm_k(int srcSel, const float* __restrict__ B,
    const float* __restrict__ bias1, const float* __restrict__ bias2,
    int slot, int K)
{
    __shared__ float As[2][8][128];
    __shared__ float Bs[2][8][128];
    const float* __restrict__ A = srcSel ? g_h0 : g_x;
    float* __restrict__ C = g_g[slot];
    const int N = GATES;
    const int tid = threadIdx.x;
    const int tx = tid & 15;
    const int ty = tid >> 4;
    const int mBase = blockIdx.y * 128;
    const int nBase = blockIdx.x * 128;
    const int ldRow = tid >> 1;
    const int ldCol = (tid & 1) * 4;
    const float* Ap = A + (size_t)(mBase + ldRow) * K + ldCol;
    const float* Bp = B + (size_t)(nBase + ldRow) * K + ldCol;

    float acc[8][8];
#pragma unroll
    for (int i = 0; i < 8; i++)
#pragma unroll
        for (int j = 0; j < 8; j++) acc[i][j] = 0.f;

    float4 av = *(const float4*)Ap;
    float4 bv = *(const float4*)Bp;
    As[0][ldCol + 0][ldRow] = av.x; As[0][ldCol + 1][ldRow] = av.y;
    As[0][ldCol + 2][ldRow] = av.z; As[0][ldCol + 3][ldRow] = av.w;
    Bs[0][ldCol + 0][ldRow] = bv.x; Bs[0][ldCol + 1][ldRow] = bv.y;
    Bs[0][ldCol + 2][ldRow] = bv.z; Bs[0][ldCol + 3][ldRow] = bv.w;
    __syncthreads();

    const int nk = K >> 3;
    for (int kt = 0; kt < nk; kt++) {
        const int cur = kt & 1;
        if (kt + 1 < nk) {
            av = *(const float4*)(Ap + (kt + 1) * 8);
            bv = *(const float4*)(Bp + (kt + 1) * 8);
        }
#pragma unroll
        for (int kk = 0; kk < 8; kk++) {
            float4 a0 = *(const float4*)&As[cur][kk][ty * 8];
            float4 a1 = *(const float4*)&As[cur][kk][ty * 8 + 4];
            float4 b0 = *(const float4*)&Bs[cur][kk][tx * 8];
            float4 b1 = *(const float4*)&Bs[cur][kk][tx * 8 + 4];
            float ar[8] = {a0.x, a0.y, a0.z, a0.w, a1.x, a1.y, a1.z, a1.w};
            float br[8] = {b0.x, b0.y, b0.z, b0.w, b1.x, b1.y, b1.z, b1.w};
#pragma unroll
            for (int i = 0; i < 8; i++)
#pragma unroll
                for (int j = 0; j < 8; j++)
                    acc[i][j] += ar[i] * br[j];
        }
        if (kt + 1 < nk) {
            const int nxt = cur ^ 1;
            As[nxt][ldCol + 0][ldRow] = av.x; As[nxt][ldCol + 1][ldRow] = av.y;
            As[nxt][ldCol + 2][ldRow] = av.z; As[nxt][ldCol + 3][ldRow] = av.w;
            Bs[nxt][ldCol + 0][ldRow] = bv.x; Bs[nxt][ldCol + 1][ldRow] = bv.y;
            Bs[nxt][ldCol + 2][ldRow] = bv.z; Bs[nxt][ldCol + 3][ldRow] = bv.w;
            __syncthreads();
        }
    }
#pragma unroll
    for (int i = 0; i < 8; i++) {
        int m = mBase + ty * 8 + i;
        float* Cp = C + (size_t)m * N + nBase + tx * 8;
#pragma unroll
        for (int j = 0; j < 8; j++) {
            int n = nBase + tx * 8 + j;
            Cp[j] = acc[i][j] + bias1[n] + bias2[n];
        }
    }
}

// ---------------- recurrent LSTM scan (persistent, 128 co-resident blocks) ------
// blocks 0..63: forward dir, 64..127: backward dir. Block b owns h indices b*8..b*8+7.
// Warp w: gate = w>>3 (i,f,g,o), jl = w&7; W_hh row held in 16 regs per thread.
__global__ __launch_bounds__(1024, 1) void scan_k(const float* __restrict__ whhf,
    const float* __restrict__ whhb, int outSel, unsigned base)
{
    __shared__ float4 hs4[128];
    __shared__ float sg[4][8];
    float* __restrict__ hout = outSel ? g_h1 : g_h0;
    const int tid = threadIdx.x;
    const int bx = blockIdx.x;
    const int dir = bx >> 6;          // 0 fwd, 1 bwd
    const int b = bx & (NSCAN - 1);
    const int w = tid >> 5;
    const int lane = tid & 31;
    const int gate = w >> 3;
    const int jl = w & 7;
    const int row = gate * HID + b * 8 + jl;
    const float* __restrict__ whh = dir ? whhb : whhf;
    const float* __restrict__ gp = g_g[dir];
    volatile unsigned* vf = (volatile unsigned*)g_flags;

    // weight rows -> registers (16 floats per thread)
    const float4* wr = (const float4*)(whh + (size_t)row * HID) + lane * 4;
    float4 w0 = wr[0], w1 = wr[1], w2 = wr[2], w3 = wr[3];

    float c = 0.f;
    for (int t = 0; t < TT; t++) {
        const int t_idx = dir ? (TT - 1 - t) : t;
        float gval = 0.f;
        if (lane == 0) gval = __ldg(gp + (size_t)t_idx * GATES + row);  // overlap w/ dot
        if (tid < 128) {
            float4 v = make_float4(0.f, 0.f, 0.f, 0.f);
            if (t > 0) {
                const int p_idx = dir ? (t_idx + 1) : (t_idx - 1);
                v = __ldcg(((const float4*)(hout + (size_t)p_idx * 1024 + dir * HID)) + tid);
            }
            hs4[tid] = v;
        }
        __syncthreads();
        float4 h0v = hs4[lane * 4 + 0];
        float4 h1v = hs4[lane * 4 + 1];
        float4 h2v = hs4[lane * 4 + 2];
        float4 h3v = hs4[lane * 4 + 3];
        float acc = w0.x * h0v.x + w0.y * h0v.y + w0.z * h0v.z + w0.w * h0v.w;
        acc += w1.x * h1v.x + w1.y * h1v.y + w1.z * h1v.z + w1.w * h1v.w;
        acc += w2.x * h2v.x + w2.y * h2v.y + w2.z * h2v.z + w2.w * h2v.w;
        acc += w3.x * h3v.x + w3.y * h3v.y + w3.z * h3v.z + w3.w * h3v.w;
#pragma unroll
        for (int off = 16; off; off >>= 1) acc += __shfl_xor_sync(0xffffffffu, acc, off);
        if (lane == 0) sg[gate][jl] = acc + gval;
        __syncthreads();
        if (tid < 8) {
            float ig = fsig(sg[0][tid]);
            float fg = fsig(sg[1][tid]);
            float gg = ftanh(sg[2][tid]);
            float og = fsig(sg[3][tid]);
            c = fg * c + ig * gg;
            float h = og * ftanh(c);
            hout[(size_t)t_idx * 1024 + dir * HID + b * 8 + tid] = h;
            __threadfence();   // push h to device scope before flag
        }
        __syncthreads();
        if (tid == 0) {
            __threadfence();
            vf[bx] = base + t + 1;
        }
        const unsigned tgt = base + t + 1;
        bool done;
        do {
            int ok = (tid < 2 * NSCAN) ? (vf[tid] >= tgt) : 1;
            done = __syncthreads_and(ok);
        } while (!done);
        __threadfence();       // acquire before reading peers' h next step
    }
}

// ---------------- final linear: feats[t,j] = h1[t]·lin_w[j] + lin_b[j] -----------
__global__ __launch_bounds__(512) void feats_k(const float* __restrict__ lin_w,
    const float* __restrict__ lin_b)
{
    __shared__ float hs[1024];
    int t = blockIdx.x;
    for (int i = threadIdx.x; i < 1024; i += 512) hs[i] = g_h1[(size_t)t * 1024 + i];
    __syncthreads();
    int w = threadIdx.x >> 5, lane = threadIdx.x & 31;
    for (int j = w; j < KTAGS; j += 16) {
        float s = 0.f;
        const float* wrow = lin_w + (size_t)j * 1024;
        for (int k = lane; k < 1024; k += 32) s += wrow[k] * hs[k];
#pragma unroll
        for (int off = 16; off; off >>= 1) s += __shfl_xor_sync(0xffffffffu, s, off);
        if (lane == 0) g_feats[(size_t)t * KTAGS + j] = s + lin_b[j];
    }
}

// ---------------- CRF: forward algorithm + gold score + output -------------------
// 384 threads: tid = g*48 + j is WRONG ordering for coalescing; use j = tid%48, g = tid/48
__global__ __launch_bounds__(384) void crf_k(const float* __restrict__ trans,
    const int* __restrict__ tags, const int* __restrict__ seqlen, float* __restrict__ out)
{
    __shared__ float Tt[KTAGS * KTAGS];   // Tt[i*48+j] = trans[j*48+i]
    __shared__ float alpha[KTAGS];
    __shared__ float mj[KTAGS];
    __shared__ float red[8 * KTAGS];
    __shared__ float fs[KTAGS];
    __shared__ float scArr[384];
    const int tid = threadIdx.x;
    const int j = tid % 48;
    const int g = tid / 48;

    for (int idx = tid; idx < KTAGS * KTAGS; idx += 384) {
        int i = idx / 48, jj = idx % 48;
        Tt[idx] = trans[jj * 48 + i];
    }
    // gold-path score (parallel partial sums)
    float sc = 0.f;
    for (int t = tid; t < TT; t += 384) {
        int cur = tags[t];
        int prev = t ? tags[t - 1] : START_TAG;
        sc += trans[cur * 48 + prev] + g_feats[(size_t)t * KTAGS + cur];
    }
    scArr[tid] = sc;
    if (tid < KTAGS) alpha[tid] = (tid == START_TAG) ? 0.f : NEGV;
    __syncthreads();

    for (int t = 0; t < TT; t++) {
        if (tid < KTAGS) fs[tid] = g_feats[(size_t)t * KTAGS + tid];
        float m = -3.0e38f;
#pragma unroll
        for (int ii = 0; ii < 6; ii++) {
            int i = g * 6 + ii;
            m = fmaxf(m, alpha[i] + Tt[i * 48 + j]);
        }
        red[g * 48 + j] = m;
        __syncthreads();
        if (g == 0) {
            float mm = red[j];
#pragma unroll
            for (int gg = 1; gg < 8; gg++) mm = fmaxf(mm, red[gg * 48 + j]);
            mj[j] = mm;
        }
        __syncthreads();
        float mv = mj[j];
        float s = 0.f;
#pragma unroll
        for (int ii = 0; ii < 6; ii++) {
            int i = g * 6 + ii;
            s += __expf(alpha[i] + Tt[i * 48 + j] - mv);
        }
        red[g * 48 + j] = s;
        __syncthreads();
        if (g == 0) {
            float ss = red[j];
#pragma unroll
            for (int gg = 1; gg < 8; gg++) ss += red[gg * 48 + j];
            alpha[j] = mj[j] + __logf(ss) + fs[j];
        }
        __syncthreads();
    }

    if (tid == 0) {
        float score = 0.f;
        for (int k = 0; k < 384; k++) score += scArr[k];
        score += trans[END_TAG * 48 + tags[TT - 1]];
        float mm = -3.0e38f;
        for (int k = 0; k < KTAGS; k++) mm = fmaxf(mm, alpha[k] + trans[END_TAG * 48 + k]);
        float ss = 0.f;
        for (int k = 0; k < KTAGS; k++) ss += __expf(alpha[k] + trans[END_TAG * 48 + k] - mm);
        float logz = mm + __logf(ss);
        out[0] = (logz - score) / (float)seqlen[0];
    }
}

// ---------------- launch sequence ------------------------------------------------
extern "C" void kernel_launch(void* const* d_in, const int* in_sizes, int n_in,
                              void* d_out, int out_size)
{
    (void)in_sizes; (void)n_in; (void)out_size;
    const int* tokens = (const int*)d_in[0];
    const int* tags   = (const int*)d_in[1];
    const int* seqlen = (const int*)d_in[2];
    const float* embed = (const float*)d_in[3];
    const float* w_ih_l0_f = (const float*)d_in[4];
    const float* w_hh_l0_f = (const float*)d_in[5];
    const float* b_ih_l0_f = (const float*)d_in[6];
    const float* b_hh_l0_f = (const float*)d_in[7];
    const float* w_ih_l0_b = (const float*)d_in[8];
    const float* w_hh_l0_b = (const float*)d_in[9];
    const float* b_ih_l0_b = (const float*)d_in[10];
    const float* b_hh_l0_b = (const float*)d_in[11];
    const float* w_ih_l1_f = (const float*)d_in[12];
    const float* w_hh_l1_f = (const float*)d_in[13];
    const float* b_ih_l1_f = (const float*)d_in[14];
    const float* b_hh_l1_f = (const float*)d_in[15];
    const float* w_ih_l1_b = (const float*)d_in[16];
    const float* w_hh_l1_b = (const float*)d_in[17];
    const float* b_ih_l1_b = (const float*)d_in[18];
    const float* b_hh_l1_b = (const float*)d_in[19];
    const float* lin_w = (const float*)d_in[20];
    const float* lin_b = (const float*)d_in[21];
    const float* trans = (const float*)d_in[22];
    float* out = (float*)d_out;

    init_k<<<1, 128>>>();
    embed_k<<<TT, 64>>>(tokens, embed);

    dim3 gg(GATES / 128, TT / 128);
    // layer 0 input projections
    gemm_k<<<gg, 256>>>(0, w_ih_l0_f, b_ih_l0_f, b_hh_l0_f, 0, EMB);
    gemm_k<<<gg, 256>>>(0, w_ih_l0_b, b_ih_l0_b, b_hh_l0_b, 1, EMB);
    // layer 0 recurrence (fwd + bwd concurrently)
    scan_k<<<2 * NSCAN, 1024>>>(w_hh_l0_f, w_hh_l0_b, 0, 0u);
    // layer 1 input projections (input = h0 concat)
    gemm_k<<<gg, 256>>>(1, w_ih_l1_f, b_ih_l1_f, b_hh_l1_f, 0, 1024);
    gemm_k<<<gg, 256>>>(1, w_ih_l1_b, b_ih_l1_b, b_hh_l1_b, 1, 1024);
    // layer 1 recurrence
    scan_k<<<2 * NSCAN, 1024>>>(w_hh_l1_f, w_hh_l1_b, 1, (unsigned)TT);
    // emissions
    feats_k<<<TT, 512>>>(lin_w, lin_b);
    // CRF forward + score + output
    crf_k<<<1, 384>>>(trans, tags, seqlen, out);
}

// round 2
// speedup vs baseline: 1.0287x; 1.0287x over previous
#include <cuda_runtime.h>

#define TT     2048
#define HID    512
#define EMB    256
#define GATES  2048
#define KTAGS  48
#define START_TAG 45
#define END_TAG   46
#define NEGV  -100000.0f
#define NSCAN  64   // blocks per direction in the recurrent scan

// ---------------- device-global scratch ----------------
__device__ __align__(128) float g_x[TT * EMB];
__device__ __align__(128) float g_g[2][TT * GATES];
__device__ __align__(128) float g_h0[TT * 1024];
__device__ __align__(128) float g_h1[TT * 1024];
__device__ __align__(128) float g_feats[TT * KTAGS];
__device__ unsigned g_flags[2 * NSCAN];

__device__ __forceinline__ float fsig(float x) {
    return __fdividef(1.0f, 1.0f + __expf(-x));
}
__device__ __forceinline__ float ftanh(float x) {
    return 2.0f * __fdividef(1.0f, 1.0f + __expf(-2.0f * x)) - 1.0f;
}
__device__ __forceinline__ unsigned ld_acq(const unsigned* p) {
    unsigned v;
    asm volatile("ld.global.acquire.gpu.u32 %0, [%1];" : "=r"(v) : "l"(p) : "memory");
    return v;
}
__device__ __forceinline__ void st_rel(unsigned* p, unsigned v) {
    asm volatile("st.global.release.gpu.u32 [%0], %1;" :: "l"(p), "r"(v) : "memory");
}

__global__ void init_k() {
    if (threadIdx.x < 2 * NSCAN) g_flags[threadIdx.x] = 0u;
}

__global__ void embed_k(const int* __restrict__ tokens, const float* __restrict__ emb) {
    int t = blockIdx.x;
    int tok = tokens[t];
    const float4* src = (const float4*)(emb + (size_t)tok * EMB);
    float4* dst = (float4*)(g_x + (size_t)t * EMB);
    for (int i = threadIdx.x; i < EMB / 4; i += blockDim.x) dst[i] = src[i];
}

// ---------------- fp32 GEMM (NT): C[t,n] = sum_k A[t,k]*B[n,k] + b1[n]+b2[n] -----
__global__ __launch_bounds__(256) void gemm_k(int srcSel, const float* __restrict__ B,
    const float* __restrict__ bias1, const float* __restrict__ bias2,
    int slot, int K)
{
    __shared__ float As[2][8][128];
    __shared__ float Bs[2][8][128];
    const float* __restrict__ A = srcSel ? g_h0 : g_x;
    float* __restrict__ C = g_g[slot];
    const int N = GATES;
    const int tid = threadIdx.x;
    const int tx = tid & 15;
    const int ty = tid >> 4;
    const int mBase = blockIdx.y * 128;
    const int nBase = blockIdx.x * 128;
    const int ldRow = tid >> 1;
    const int ldCol = (tid & 1) * 4;
    const float* Ap = A + (size_t)(mBase + ldRow) * K + ldCol;
    const float* Bp = B + (size_t)(nBase + ldRow) * K + ldCol;

    float acc[8][8];
#pragma unroll
    for (int i = 0; i < 8; i++)
#pragma unroll
        for (int j = 0; j < 8; j++) acc[i][j] = 0.f;

    float4 av = *(const float4*)Ap;
    float4 bv = *(const float4*)Bp;
    As[0][ldCol + 0][ldRow] = av.x; As[0][ldCol + 1][ldRow] = av.y;
    As[0][ldCol + 2][ldRow] = av.z; As[0][ldCol + 3][ldRow] = av.w;
    Bs[0][ldCol + 0][ldRow] = bv.x; Bs[0][ldCol + 1][ldRow] = bv.y;
    Bs[0][ldCol + 2][ldRow] = bv.z; Bs[0][ldCol + 3][ldRow] = bv.w;
    __syncthreads();

    const int nk = K >> 3;
    for (int kt = 0; kt < nk; kt++) {
        const int cur = kt & 1;
        if (kt + 1 < nk) {
            av = *(const float4*)(Ap + (kt + 1) * 8);
            bv = *(const float4*)(Bp + (kt + 1) * 8);
        }
#pragma unroll
        for (int kk = 0; kk < 8; kk++) {
            float4 a0 = *(const float4*)&As[cur][kk][ty * 8];
            float4 a1 = *(const float4*)&As[cur][kk][ty * 8 + 4];
            float4 b0 = *(const float4*)&Bs[cur][kk][tx * 8];
            float4 b1 = *(const float4*)&Bs[cur][kk][tx * 8 + 4];
            float ar[8] = {a0.x, a0.y, a0.z, a0.w, a1.x, a1.y, a1.z, a1.w};
            float br[8] = {b0.x, b0.y, b0.z, b0.w, b1.x, b1.y, b1.z, b1.w};
#pragma unroll
            for (int i = 0; i < 8; i++)
#pragma unroll
                for (int j = 0; j < 8; j++)
                    acc[i][j] += ar[i] * br[j];
        }
        if (kt + 1 < nk) {
            const int nxt = cur ^ 1;
            As[nxt][ldCol + 0][ldRow] = av.x; As[nxt][ldCol + 1][ldRow] = av.y;
            As[nxt][ldCol + 2][ldRow] = av.z; As[nxt][ldCol + 3][ldRow] = av.w;
            Bs[nxt][ldCol + 0][ldRow] = bv.x; Bs[nxt][ldCol + 1][ldRow] = bv.y;
            Bs[nxt][ldCol + 2][ldRow] = bv.z; Bs[nxt][ldCol + 3][ldRow] = bv.w;
            __syncthreads();
        }
    }
#pragma unroll
    for (int i = 0; i < 8; i++) {
        int m = mBase + ty * 8 + i;
        float* Cp = C + (size_t)m * N + nBase + tx * 8;
#pragma unroll
        for (int j = 0; j < 8; j++) {
            int n = nBase + tx * 8 + j;
            Cp[j] = acc[i][j] + bias1[n] + bias2[n];
        }
    }
}

// ---------------- recurrent LSTM scan (persistent, 128 co-resident blocks) ------
// blocks 0..63 forward, 64..127 backward. Block b owns h[b*8..b*8+8) of its dir.
// Warp w: gate=w>>3, jl=w&7 -> row = gate*512 + b*8 + jl.
// Lane l covers h indices {l+32k, k=0..15} (conflict-free smem).
// Sync: per-lane acquire spin on exactly the flag guarding the h-chunk it stages;
// one release store per block per step. No MEMBAR, no BAR inside spin loops.
__global__ __launch_bounds__(1024, 1) void scan_k(const float* __restrict__ whhf,
    const float* __restrict__ whhb, int outSel, unsigned base)
{
    __shared__ float hs[512];
    __shared__ float sg[4][8];
    float* __restrict__ hout = outSel ? g_h1 : g_h0;
    const int tid = threadIdx.x;
    const int bx = blockIdx.x;
    const int dir = bx >> 6;
    const int b = bx & (NSCAN - 1);
    const int w = tid >> 5;
    const int lane = tid & 31;
    const int gate = w >> 3;
    const int jl = w & 7;
    const int row = gate * HID + b * 8 + jl;
    const float* __restrict__ whh = dir ? whhb : whhf;
    const float* __restrict__ gp = g_g[dir];

    // W_hh row, stride-32 partition -> 16 regs/thread
    float wreg[16];
#pragma unroll
    for (int k = 0; k < 16; k++) wreg[k] = whh[(size_t)row * HID + lane + 32 * k];

    // staging threads: tid<128, each stages one float4 (h floats 4*tid..4*tid+3),
    // guarded by producing block's flag (dir*64 + tid/2)
    const unsigned* myFlag = g_flags + (dir * NSCAN + (tid >> 1));
    float c = 0.f;

    for (int t = 0; t < TT; t++) {
        const int t_idx = dir ? (TT - 1 - t) : t;
        float gval = 0.f;
        if (lane == 0) gval = __ldg(gp + (size_t)t_idx * GATES + row);  // prefetch, overlaps poll
        if (tid < 128) {
            float4 v = make_float4(0.f, 0.f, 0.f, 0.f);
            if (t > 0) {
                const unsigned tgt = base + (unsigned)t;   // step t-1 done => flag >= base+t
                while (ld_acq(myFlag) < tgt) { }
                const int p_idx = dir ? (t_idx + 1) : (t_idx - 1);
                v = __ldcg((const float4*)(hout + (size_t)p_idx * 1024 + dir * HID) + tid);
            }
            ((float4*)hs)[tid] = v;
        }
        __syncthreads();   // stage ready
        float acc = 0.f;
#pragma unroll
        for (int k = 0; k < 16; k++) acc = fmaf(wreg[k], hs[lane + 32 * k], acc);
#pragma unroll
        for (int off = 16; off; off >>= 1) acc += __shfl_xor_sync(0xffffffffu, acc, off);
        if (lane == 0) sg[gate][jl] = acc + gval;
        __syncthreads();   // sg ready
        if (tid < 8) {
            float ig = fsig(sg[0][tid]);
            float fg = fsig(sg[1][tid]);
            float gg = ftanh(sg[2][tid]);
            float og = fsig(sg[3][tid]);
            c = fg * c + ig * gg;
            float h = og * ftanh(c);
            __stcg(hout + (size_t)t_idx * 1024 + dir * HID + b * 8 + tid, h);
        }
        __syncthreads();   // h stores ordered before flag (block scope)
        if (tid == 0) st_rel(g_flags + bx, base + (unsigned)t + 1u);  // gpu-scope release
    }
}

// ---------------- final linear: feats[t,j] = h1[t]·lin_w[j] + lin_b[j] -----------
__global__ __launch_bounds__(512) void feats_k(const float* __restrict__ lin_w,
    const float* __restrict__ lin_b)
{
    __shared__ float hsm[1024];
    int t = blockIdx.x;
    for (int i = threadIdx.x; i < 1024; i += 512) hsm[i] = g_h1[(size_t)t * 1024 + i];
    __syncthreads();
    int w = threadIdx.x >> 5, lane = threadIdx.x & 31;
    for (int j = w; j < KTAGS; j += 16) {
        float s = 0.f;
        const float* wrow = lin_w + (size_t)j * 1024;
        for (int k = lane; k < 1024; k += 32) s += wrow[k] * hsm[k];
#pragma unroll
        for (int off = 16; off; off >>= 1) s += __shfl_xor_sync(0xffffffffu, s, off);
        if (lane == 0) g_feats[(size_t)t * KTAGS + j] = s + lin_b[j];
    }
}

// ---------------- CRF: 384 threads, j = tid>>3 (0..47), sub = tid&7 --------------
// Each 8-thread subgroup handles one destination tag j; i-range split 6 per sub.
// Transition row held in registers; shuffle all-reduce; one BAR per step.
__global__ __launch_bounds__(384) void crf_k(const float* __restrict__ trans,
    const int* __restrict__ tags, const int* __restrict__ seqlen, float* __restrict__ out)
{
    __shared__ float alpha[2][KTAGS];
    __shared__ float scRed[384];
    const int tid = threadIdx.x;
    const int j = tid >> 3;
    const int sub = tid & 7;

    float tw[6];
#pragma unroll
    for (int kk = 0; kk < 6; kk++) tw[kk] = __ldg(trans + j * 48 + sub * 6 + kk);

    // gold-path score partials
    float sc = 0.f;
    for (int t = tid; t < TT; t += 384) {
        int cur = tags[t];
        int prev = t ? tags[t - 1] : START_TAG;
        sc += __ldg(trans + cur * 48 + prev) + g_feats[(size_t)t * KTAGS + cur];
    }
    scRed[tid] = sc;
    if (tid < KTAGS) alpha[0][tid] = (tid == START_TAG) ? 0.f : NEGV;
    __syncthreads();

    int p = 0;
    for (int t = 0; t < TT; t++) {
        float gf = __ldg(g_feats + (size_t)t * KTAGS + j);
        float a[6];
#pragma unroll
        for (int kk = 0; kk < 6; kk++) a[kk] = alpha[p][sub * 6 + kk] + tw[kk];
        float m = a[0];
#pragma unroll
        for (int kk = 1; kk < 6; kk++) m = fmaxf(m, a[kk]);
#pragma unroll
        for (int off = 1; off < 8; off <<= 1) m = fmaxf(m, __shfl_xor_sync(0xffffffffu, m, off));
        float s = 0.f;
#pragma unroll
        for (int kk = 0; kk < 6; kk++) s += __expf(a[kk] - m);
#pragma unroll
        for (int off = 1; off < 8; off <<= 1) s += __shfl_xor_sync(0xffffffffu, s, off);
        if (sub == 0) alpha[p ^ 1][j] = m + __logf(s) + gf;
        __syncthreads();
        p ^= 1;
    }

    if (tid == 0) {
        float score = 0.f;
        for (int k = 0; k < 384; k++) score += scRed[k];
        score += trans[END_TAG * 48 + tags[TT - 1]];
        float mm = -3.0e38f;
        for (int k = 0; k < KTAGS; k++) mm = fmaxf(mm, alpha[p][k] + trans[END_TAG * 48 + k]);
        float ss = 0.f;
        for (int k = 0; k < KTAGS; k++) ss += __expf(alpha[p][k] + trans[END_TAG * 48 + k] - mm);
        float logz = mm + __logf(ss);
        out[0] = (logz - score) / (float)seqlen[0];
    }
}

// ---------------- launch sequence ------------------------------------------------
extern "C" void kernel_launch(void* const* d_in, const int* in_sizes, int n_in,
                              void* d_out, int out_size)
{
    (void)in_sizes; (void)n_in; (void)out_size;
    const int* tokens = (const int*)d_in[0];
    const int* tags   = (const int*)d_in[1];
    const int* seqlen = (const int*)d_in[2];
    const float* embed = (const float*)d_in[3];
    const float* w_ih_l0_f = (const float*)d_in[4];
    const float* w_hh_l0_f = (const float*)d_in[5];
    const float* b_ih_l0_f = (const float*)d_in[6];
    const float* b_hh_l0_f = (const float*)d_in[7];
    const float* w_ih_l0_b = (const float*)d_in[8];
    const float* w_hh_l0_b = (const float*)d_in[9];
    const float* b_ih_l0_b = (const float*)d_in[10];
    const float* b_hh_l0_b = (const float*)d_in[11];
    const float* w_ih_l1_f = (const float*)d_in[12];
    const float* w_hh_l1_f = (const float*)d_in[13];
    const float* b_ih_l1_f = (const float*)d_in[14];
    const float* b_hh_l1_f = (const float*)d_in[15];
    const float* w_ih_l1_b = (const float*)d_in[16];
    const float* w_hh_l1_b = (const float*)d_in[17];
    const float* b_ih_l1_b = (const float*)d_in[18];
    const float* b_hh_l1_b = (const float*)d_in[19];
    const float* lin_w = (const float*)d_in[20];
    const float* lin_b = (const float*)d_in[21];
    const float* trans = (const float*)d_in[22];
    float* out = (float*)d_out;

    init_k<<<1, 128>>>();
    embed_k<<<TT, 64>>>(tokens, embed);

    dim3 gg(GATES / 128, TT / 128);
    gemm_k<<<gg, 256>>>(0, w_ih_l0_f, b_ih_l0_f, b_hh_l0_f, 0, EMB);
    gemm_k<<<gg, 256>>>(0, w_ih_l0_b, b_ih_l0_b, b_hh_l0_b, 1, EMB);
    scan_k<<<2 * NSCAN, 1024>>>(w_hh_l0_f, w_hh_l0_b, 0, 0u);
    gemm_k<<<gg, 256>>>(1, w_ih_l1_f, b_ih_l1_f, b_hh_l1_f, 0, 1024);
    gemm_k<<<gg, 256>>>(1, w_ih_l1_b, b_ih_l1_b, b_hh_l1_b, 1, 1024);
    scan_k<<<2 * NSCAN, 1024>>>(w_hh_l1_f, w_hh_l1_b, 1, (unsigned)TT);
    feats_k<<<TT, 512>>>(lin_w, lin_b);
    crf_k<<<1, 384>>>(trans, tags, seqlen, out);
}

// round 3
// speedup vs baseline: 3.2759x; 3.1844x over previous
#include <cuda_runtime.h>

#define TT     2048
#define HID    512
#define EMB    256
#define GATES  2048
#define KTAGS  48
#define START_TAG 45
#define END_TAG   46
#define NEGV  -100000.0f
#define NSCAN  64    // blocks per direction in the recurrent scan
#define FPAD   32    // pad each flag to its own 128-B line

// ---------------- device-global scratch ----------------
__device__ __align__(128) float g_x[TT * EMB];
__device__ __align__(128) float g_g[2][TT * GATES];
__device__ __align__(128) float g_h0[TT * 1024];
__device__ __align__(128) float g_h1[TT * 1024];
__device__ __align__(128) float g_feats[TT * KTAGS];
__device__ __align__(128) unsigned g_flags[2 * NSCAN * FPAD];

__device__ __forceinline__ float fsig(float x) {
    return __fdividef(1.0f, 1.0f + __expf(-x));
}
__device__ __forceinline__ float ftanh(float x) {
    return 2.0f * __fdividef(1.0f, 1.0f + __expf(-2.0f * x)) - 1.0f;
}
__device__ __forceinline__ unsigned ld_acq(const unsigned* p) {
    unsigned v;
    asm volatile("ld.global.acquire.gpu.u32 %0, [%1];" : "=r"(v) : "l"(p) : "memory");
    return v;
}
__device__ __forceinline__ void red_rel_add(unsigned* p, unsigned v) {
    asm volatile("red.release.gpu.global.add.u32 [%0], %1;" :: "l"(p), "r"(v) : "memory");
}

__global__ void init_k() {
    for (int i = threadIdx.x; i < 2 * NSCAN * FPAD; i += blockDim.x) g_flags[i] = 0u;
}

__global__ void dummy_k() {}   // launch-index filler so ncu -s 5 captures scan_k

__global__ void embed_k(const int* __restrict__ tokens, const float* __restrict__ emb) {
    int t = blockIdx.x;
    int tok = tokens[t];
    const float4* src = (const float4*)(emb + (size_t)tok * EMB);
    float4* dst = (float4*)(g_x + (size_t)t * EMB);
    for (int i = threadIdx.x; i < EMB / 4; i += blockDim.x) dst[i] = src[i];
}

// ---------------- fp32 GEMM (NT): C[t,n] = sum_k A[t,k]*B[n,k] + b1[n]+b2[n] -----
__global__ __launch_bounds__(256) void gemm_k(int srcSel, const float* __restrict__ B,
    const float* __restrict__ bias1, const float* __restrict__ bias2,
    int slot, int K)
{
    __shared__ float As[2][8][128];
    __shared__ float Bs[2][8][128];
    const float* __restrict__ A = srcSel ? g_h0 : g_x;
    float* __restrict__ C = g_g[slot];
    const int N = GATES;
    const int tid = threadIdx.x;
    const int tx = tid & 15;
    const int ty = tid >> 4;
    const int mBase = blockIdx.y * 128;
    const int nBase = blockIdx.x * 128;
    const int ldRow = tid >> 1;
    const int ldCol = (tid & 1) * 4;
    const float* Ap = A + (size_t)(mBase + ldRow) * K + ldCol;
    const float* Bp = B + (size_t)(nBase + ldRow) * K + ldCol;

    float acc[8][8];
#pragma unroll
    for (int i = 0; i < 8; i++)
#pragma unroll
        for (int j = 0; j < 8; j++) acc[i][j] = 0.f;

    float4 av = *(const float4*)Ap;
    float4 bv = *(const float4*)Bp;
    As[0][ldCol + 0][ldRow] = av.x; As[0][ldCol + 1][ldRow] = av.y;
    As[0][ldCol + 2][ldRow] = av.z; As[0][ldCol + 3][ldRow] = av.w;
    Bs[0][ldCol + 0][ldRow] = bv.x; Bs[0][ldCol + 1][ldRow] = bv.y;
    Bs[0][ldCol + 2][ldRow] = bv.z; Bs[0][ldCol + 3][ldRow] = bv.w;
    __syncthreads();

    const int nk = K >> 3;
    for (int kt = 0; kt < nk; kt++) {
        const int cur = kt & 1;
        if (kt + 1 < nk) {
            av = *(const float4*)(Ap + (kt + 1) * 8);
            bv = *(const float4*)(Bp + (kt + 1) * 8);
        }
#pragma unroll
        for (int kk = 0; kk < 8; kk++) {
            float4 a0 = *(const float4*)&As[cur][kk][ty * 8];
            float4 a1 = *(const float4*)&As[cur][kk][ty * 8 + 4];
            float4 b0 = *(const float4*)&Bs[cur][kk][tx * 8];
            float4 b1 = *(const float4*)&Bs[cur][kk][tx * 8 + 4];
            float ar[8] = {a0.x, a0.y, a0.z, a0.w, a1.x, a1.y, a1.z, a1.w};
            float br[8] = {b0.x, b0.y, b0.z, b0.w, b1.x, b1.y, b1.z, b1.w};
#pragma unroll
            for (int i = 0; i < 8; i++)
#pragma unroll
                for (int j = 0; j < 8; j++)
                    acc[i][j] += ar[i] * br[j];
        }
        if (kt + 1 < nk) {
            const int nxt = cur ^ 1;
            As[nxt][ldCol + 0][ldRow] = av.x; As[nxt][ldCol + 1][ldRow] = av.y;
            As[nxt][ldCol + 2][ldRow] = av.z; As[nxt][ldCol + 3][ldRow] = av.w;
            Bs[nxt][ldCol + 0][ldRow] = bv.x; Bs[nxt][ldCol + 1][ldRow] = bv.y;
            Bs[nxt][ldCol + 2][ldRow] = bv.z; Bs[nxt][ldCol + 3][ldRow] = bv.w;
            __syncthreads();
        }
    }
#pragma unroll
    for (int i = 0; i < 8; i++) {
        int m = mBase + ty * 8 + i;
        float* Cp = C + (size_t)m * N + nBase + tx * 8;
#pragma unroll
        for (int j = 0; j < 8; j++) {
            int n = nBase + tx * 8 + j;
            Cp[j] = acc[i][j] + bias1[n] + bias2[n];
        }
    }
}

// ---------------- recurrent LSTM scan (persistent, 128 co-resident blocks) ------
// blocks 0..63 forward, 64..127 backward. Block b owns h[b*8..b*8+8) of its dir.
// Warp w: gate=w>>3, jl=w&7 -> row = gate*512 + b*8 + jl; W_hh row in 16 regs.
// Flags: one 128B line per block; counter += 8 per step via red.release from the
// 8 h-producing threads; consumers acquire-poll (with nanosleep backoff) the flag
// guarding the chunk they stage. 2 __syncthreads per step, no other fences.
__global__ __launch_bounds__(1024, 1) void scan_k(const float* __restrict__ whhf,
    const float* __restrict__ whhb, int outSel, unsigned base)
{
    __shared__ float hs[512];
    __shared__ float sg[4][8];
    float* __restrict__ hout = outSel ? g_h1 : g_h0;
    const int tid = threadIdx.x;
    const int bx = blockIdx.x;
    const int dir = bx >> 6;
    const int b = bx & (NSCAN - 1);
    const int lane = tid & 31;
    const int gate = tid >> 8;              // (tid>>5)>>3
    const int jl = (tid >> 5) & 7;
    const int row = gate * HID + b * 8 + jl;
    const float* __restrict__ whh = dir ? whhb : whhf;
    const float* __restrict__ gp = g_g[dir];

    float wreg[16];
#pragma unroll
    for (int k = 0; k < 16; k++) wreg[k] = whh[(size_t)row * HID + lane + 32 * k];

    const unsigned* myFlag = g_flags + (size_t)(dir * NSCAN + (tid >> 1)) * FPAD;
    unsigned* ourFlag = g_flags + (size_t)bx * FPAD;
    float c = 0.f;

    for (int t = 0; t < TT; t++) {
        const int t_idx = dir ? (TT - 1 - t) : t;
        float gval = 0.f;
        if (lane == 0) gval = __ldg(gp + (size_t)t_idx * GATES + row);  // prefetch
        if (tid < 128) {
            float4 v = make_float4(0.f, 0.f, 0.f, 0.f);
            if (t > 0) {
                const unsigned need = 8u * (base + (unsigned)t);
                unsigned fv = ld_acq(myFlag);
                while (fv < need) { __nanosleep(64); fv = ld_acq(myFlag); }
                const int p_idx = dir ? (t_idx + 1) : (t_idx - 1);
                v = __ldcg((const float4*)(hout + (size_t)p_idx * 1024 + dir * HID) + tid);
            }
            ((float4*)hs)[tid] = v;
        }
        __syncthreads();   // stage ready
        float acc = 0.f;
#pragma unroll
        for (int k = 0; k < 16; k++) acc = fmaf(wreg[k], hs[lane + 32 * k], acc);
#pragma unroll
        for (int off = 16; off; off >>= 1) acc += __shfl_xor_sync(0xffffffffu, acc, off);
        if (lane == 0) sg[gate][jl] = acc + gval;
        __syncthreads();   // sg ready (also isolates hs reads from next stage)
        if (tid < 8) {
            float ig = fsig(sg[0][tid]);
            float fg = fsig(sg[1][tid]);
            float gg = ftanh(sg[2][tid]);
            float og = fsig(sg[3][tid]);
            c = fg * c + ig * gg;
            float h = og * ftanh(c);
            __stcg(hout + (size_t)t_idx * 1024 + dir * HID + b * 8 + tid, h);
            red_rel_add(ourFlag, 1u);   // release: orders this thread's h store
        }
    }
}

// ---------------- final linear: feats[t,j] = h1[t]·lin_w[j] + lin_b[j] -----------
__global__ __launch_bounds__(512) void feats_k(const float* __restrict__ lin_w,
    const float* __restrict__ lin_b)
{
    __shared__ float hsm[1024];
    int t = blockIdx.x;
    for (int i = threadIdx.x; i < 1024; i += 512) hsm[i] = g_h1[(size_t)t * 1024 + i];
    __syncthreads();
    int w = threadIdx.x >> 5, lane = threadIdx.x & 31;
    for (int j = w; j < KTAGS; j += 16) {
        float s = 0.f;
        const float* wrow = lin_w + (size_t)j * 1024;
        for (int k = lane; k < 1024; k += 32) s += wrow[k] * hsm[k];
#pragma unroll
        for (int off = 16; off; off >>= 1) s += __shfl_xor_sync(0xffffffffu, s, off);
        if (lane == 0) g_feats[(size_t)t * KTAGS + j] = s + lin_b[j];
    }
}

// ---------------- CRF: 384 threads, j = tid>>3 (0..47), sub = tid&7 --------------
__global__ __launch_bounds__(384) void crf_k(const float* __restrict__ trans,
    const int* __restrict__ tags, const int* __restrict__ seqlen, float* __restrict__ out)
{
    __shared__ float alpha[2][KTAGS];
    __shared__ float scRed[384];
    const int tid = threadIdx.x;
    const int j = tid >> 3;
    const int sub = tid & 7;

    float tw[6];
#pragma unroll
    for (int kk = 0; kk < 6; kk++) tw[kk] = __ldg(trans + j * 48 + sub * 6 + kk);

    float sc = 0.f;
    for (int t = tid; t < TT; t += 384) {
        int cur = tags[t];
        int prev = t ? tags[t - 1] : START_TAG;
        sc += __ldg(trans + cur * 48 + prev) + g_feats[(size_t)t * KTAGS + cur];
    }
    scRed[tid] = sc;
    if (tid < KTAGS) alpha[0][tid] = (tid == START_TAG) ? 0.f : NEGV;
    __syncthreads();

    int p = 0;
    for (int t = 0; t < TT; t++) {
        float gf = __ldg(g_feats + (size_t)t * KTAGS + j);
        float a[6];
#pragma unroll
        for (int kk = 0; kk < 6; kk++) a[kk] = alpha[p][sub * 6 + kk] + tw[kk];
        float m = a[0];
#pragma unroll
        for (int kk = 1; kk < 6; kk++) m = fmaxf(m, a[kk]);
#pragma unroll
        for (int off = 1; off < 8; off <<= 1) m = fmaxf(m, __shfl_xor_sync(0xffffffffu, m, off));
        float s = 0.f;
#pragma unroll
        for (int kk = 0; kk < 6; kk++) s += __expf(a[kk] - m);
#pragma unroll
        for (int off = 1; off < 8; off <<= 1) s += __shfl_xor_sync(0xffffffffu, s, off);
        if (sub == 0) alpha[p ^ 1][j] = m + __logf(s) + gf;
        __syncthreads();
        p ^= 1;
    }

    if (tid == 0) {
        float score = 0.f;
        for (int k = 0; k < 384; k++) score += scRed[k];
        score += trans[END_TAG * 48 + tags[TT - 1]];
        float mm = -3.0e38f;
        for (int k = 0; k < KTAGS; k++) mm = fmaxf(mm, alpha[p][k] + trans[END_TAG * 48 + k]);
        float ss = 0.f;
        for (int k = 0; k < KTAGS; k++) ss += __expf(alpha[p][k] + trans[END_TAG * 48 + k] - mm);
        float logz = mm + __logf(ss);
        out[0] = (logz - score) / (float)seqlen[0];
    }
}

// ---------------- launch sequence ------------------------------------------------
// Order chosen so ncu (-s 5 -c 1) captures scan_k (launch index 5).
extern "C" void kernel_launch(void* const* d_in, const int* in_sizes, int n_in,
                              void* d_out, int out_size)
{
    (void)in_sizes; (void)n_in; (void)out_size;
    const int* tokens = (const int*)d_in[0];
    const int* tags   = (const int*)d_in[1];
    const int* seqlen = (const int*)d_in[2];
    const float* embed = (const float*)d_in[3];
    const float* w_ih_l0_f = (const float*)d_in[4];
    const float* w_hh_l0_f = (const float*)d_in[5];
    const float* b_ih_l0_f = (const float*)d_in[6];
    const float* b_hh_l0_f = (const float*)d_in[7];
    const float* w_ih_l0_b = (const float*)d_in[8];
    const float* w_hh_l0_b = (const float*)d_in[9];
    const float* b_ih_l0_b = (const float*)d_in[10];
    const float* b_hh_l0_b = (const float*)d_in[11];
    const float* w_ih_l1_f = (const float*)d_in[12];
    const float* w_hh_l1_f = (const float*)d_in[13];
    const float* b_ih_l1_f = (const float*)d_in[14];
    const float* b_hh_l1_f = (const float*)d_in[15];
    const float* w_ih_l1_b = (const float*)d_in[16];
    const float* w_hh_l1_b = (const float*)d_in[17];
    const float* b_ih_l1_b = (const float*)d_in[18];
    const float* b_hh_l1_b = (const float*)d_in[19];
    const float* lin_w = (const float*)d_in[20];
    const float* lin_b = (const float*)d_in[21];
    const float* trans = (const float*)d_in[22];
    float* out = (float*)d_out;

    init_k<<<1, 1024>>>();                                          // 0
    embed_k<<<TT, 64>>>(tokens, embed);                             // 1
    dim3 gg(GATES / 128, TT / 128);
    gemm_k<<<gg, 256>>>(0, w_ih_l0_f, b_ih_l0_f, b_hh_l0_f, 0, EMB);// 2
    gemm_k<<<gg, 256>>>(0, w_ih_l0_b, b_ih_l0_b, b_hh_l0_b, 1, EMB);// 3
    dummy_k<<<1, 32>>>();                                           // 4 (ncu filler)
    scan_k<<<2 * NSCAN, 1024>>>(w_hh_l0_f, w_hh_l0_b, 0, 0u);       // 5 <- profiled
    gemm_k<<<gg, 256>>>(1, w_ih_l1_f, b_ih_l1_f, b_hh_l1_f, 0, 1024);
    gemm_k<<<gg, 256>>>(1, w_ih_l1_b, b_ih_l1_b, b_hh_l1_b, 1, 1024);
    scan_k<<<2 * NSCAN, 1024>>>(w_hh_l1_f, w_hh_l1_b, 1, (unsigned)TT);
    feats_k<<<TT, 512>>>(lin_w, lin_b);
    crf_k<<<1, 384>>>(trans, tags, seqlen, out);
}

// round 4
// speedup vs baseline: 4.3964x; 1.3421x over previous
#include <cuda_runtime.h>

#define TT     2048
#define HID    512
#define EMB    256
#define GATES  2048
#define KTAGS  48
#define START_TAG 45
#define END_TAG   46
#define NEGV  -100000.0f
#define NSCAN  64    // blocks per direction in the recurrent scan

// ---------------- device-global scratch ----------------
__device__ __align__(128) float g_x[TT * EMB];
__device__ __align__(128) float g_g[2][TT * GATES];
__device__ __align__(128) float g_h0[TT * 1024];
__device__ __align__(128) float g_h1[TT * 1024];
__device__ __align__(128) float g_feats[TT * KTAGS];
// packed (float h, unsigned tag) per h-element per timestep: [t][dir*512 + j]
__device__ __align__(128) unsigned long long g_hp[TT * 1024];

__device__ __forceinline__ float fsig(float x) {
    return __fdividef(1.0f, 1.0f + __expf(-x));
}
__device__ __forceinline__ float ftanh(float x) {
    return 2.0f * __fdividef(1.0f, 1.0f + __expf(-2.0f * x)) - 1.0f;
}

// zero all tags each replay (16 MB) — graph-replay safety for the tagged-value sync
__global__ void clear_k() {
    size_t i = (size_t)blockIdx.x * blockDim.x + threadIdx.x;
    ((ulonglong2*)g_hp)[i] = make_ulonglong2(0ull, 0ull);   // 2M ulonglong2
}

__global__ void dummy_k() {}   // launch-index filler so ncu -s 5 captures scan_k

__global__ void embed_k(const int* __restrict__ tokens, const float* __restrict__ emb) {
    int t = blockIdx.x;
    int tok = tokens[t];
    const float4* src = (const float4*)(emb + (size_t)tok * EMB);
    float4* dst = (float4*)(g_x + (size_t)t * EMB);
    for (int i = threadIdx.x; i < EMB / 4; i += blockDim.x) dst[i] = src[i];
}

// ---------------- fp32 GEMM (NT): C[t,n] = sum_k A[t,k]*B[n,k] + b1[n]+b2[n] -----
__global__ __launch_bounds__(256) void gemm_k(int srcSel, const float* __restrict__ B,
    const float* __restrict__ bias1, const float* __restrict__ bias2,
    int slot, int K)
{
    __shared__ float As[2][8][128];
    __shared__ float Bs[2][8][128];
    const float* __restrict__ A = srcSel ? g_h0 : g_x;
    float* __restrict__ C = g_g[slot];
    const int N = GATES;
    const int tid = threadIdx.x;
    const int tx = tid & 15;
    const int ty = tid >> 4;
    const int mBase = blockIdx.y * 128;
    const int nBase = blockIdx.x * 128;
    const int ldRow = tid >> 1;
    const int ldCol = (tid & 1) * 4;
    const float* Ap = A + (size_t)(mBase + ldRow) * K + ldCol;
    const float* Bp = B + (size_t)(nBase + ldRow) * K + ldCol;

    float acc[8][8];
#pragma unroll
    for (int i = 0; i < 8; i++)
#pragma unroll
        for (int j = 0; j < 8; j++) acc[i][j] = 0.f;

    float4 av = *(const float4*)Ap;
    float4 bv = *(const float4*)Bp;
    As[0][ldCol + 0][ldRow] = av.x; As[0][ldCol + 1][ldRow] = av.y;
    As[0][ldCol + 2][ldRow] = av.z; As[0][ldCol + 3][ldRow] = av.w;
    Bs[0][ldCol + 0][ldRow] = bv.x; Bs[0][ldCol + 1][ldRow] = bv.y;
    Bs[0][ldCol + 2][ldRow] = bv.z; Bs[0][ldCol + 3][ldRow] = bv.w;
    __syncthreads();

    const int nk = K >> 3;
    for (int kt = 0; kt < nk; kt++) {
        const int cur = kt & 1;
        if (kt + 1 < nk) {
            av = *(const float4*)(Ap + (kt + 1) * 8);
            bv = *(const float4*)(Bp + (kt + 1) * 8);
        }
#pragma unroll
        for (int kk = 0; kk < 8; kk++) {
            float4 a0 = *(const float4*)&As[cur][kk][ty * 8];
            float4 a1 = *(const float4*)&As[cur][kk][ty * 8 + 4];
            float4 b0 = *(const float4*)&Bs[cur][kk][tx * 8];
            float4 b1 = *(const float4*)&Bs[cur][kk][tx * 8 + 4];
            float ar[8] = {a0.x, a0.y, a0.z, a0.w, a1.x, a1.y, a1.z, a1.w};
            float br[8] = {b0.x, b0.y, b0.z, b0.w, b1.x, b1.y, b1.z, b1.w};
#pragma unroll
            for (int i = 0; i < 8; i++)
#pragma unroll
                for (int j = 0; j < 8; j++)
                    acc[i][j] += ar[i] * br[j];
        }
        if (kt + 1 < nk) {
            const int nxt = cur ^ 1;
            As[nxt][ldCol + 0][ldRow] = av.x; As[nxt][ldCol + 1][ldRow] = av.y;
            As[nxt][ldCol + 2][ldRow] = av.z; As[nxt][ldCol + 3][ldRow] = av.w;
            Bs[nxt][ldCol + 0][ldRow] = bv.x; Bs[nxt][ldCol + 1][ldRow] = bv.y;
            Bs[nxt][ldCol + 2][ldRow] = bv.z; Bs[nxt][ldCol + 3][ldRow] = bv.w;
            __syncthreads();
        }
    }
#pragma unroll
    for (int i = 0; i < 8; i++) {
        int m = mBase + ty * 8 + i;
        float* Cp = C + (size_t)m * N + nBase + tx * 8;
#pragma unroll
        for (int j = 0; j < 8; j++) {
            int n = nBase + tx * 8 + j;
            Cp[j] = acc[i][j] + bias1[n] + bias2[n];
        }
    }
}

// ---------------- recurrent LSTM scan (persistent, 128 blocks x 256 threads) -----
// blocks 0..63 forward, 64..127 backward. Block b owns h[b*8..b*8+8) of its dir.
// Warp w owns h-index j=b*8+w and computes ALL FOUR gate rows (64 weight regs).
// Sync: tagged-value handshake — producer lane0 stores (tag=step+1 | h bits) as one
// 8-byte STG; consumers poll the packed words directly (LDG.128 = 2 words/thread).
// One __syncthreads per step; hs double-buffered.
__global__ __launch_bounds__(256, 1) void scan_k(const float* __restrict__ whhf,
    const float* __restrict__ whhb, int outSel, unsigned base)
{
    __shared__ float hs[2][512];
    float* __restrict__ hout = outSel ? g_h1 : g_h0;
    const int tid = threadIdx.x;
    const int bx = blockIdx.x;
    const int dir = bx >> 6;
    const int b = bx & (NSCAN - 1);
    const int w = tid >> 5;
    const int lane = tid & 31;
    const int j = b * 8 + w;                 // owned h index within dir
    const float* __restrict__ whh = dir ? whhb : whhf;
    const float* __restrict__ gp = g_g[dir];

    // 4 gate rows of W_hh for h-index j, stride-32 partition: 64 regs/thread
    float wreg[4][16];
#pragma unroll
    for (int g = 0; g < 4; g++) {
        const float* wr = whh + (size_t)(g * HID + j) * HID;
#pragma unroll
        for (int k = 0; k < 16; k++) wreg[g][k] = wr[lane + 32 * k];
    }

    float c = 0.f;
    for (int t = 0; t < TT; t++) {
        const int t_idx = dir ? (TT - 1 - t) : t;
        // preactivation prefetch: lanes 0..3 fetch the 4 gate preacts for j
        float gval = 0.f;
        if (lane < 4) gval = __ldg(gp + (size_t)t_idx * GATES + lane * HID + j);
        const int p = t & 1;
        // stage previous h (tagged-value poll; 2 packed words per thread)
        {
            uint4 v = make_uint4(0u, 0u, 0u, 0u);
            if (t > 0) {
                const unsigned need = base + (unsigned)t;
                const int p_idx = dir ? (t_idx + 1) : (t_idx - 1);
                const uint4* src = (const uint4*)(g_hp + (size_t)p_idx * 1024 + dir * HID) + tid;
                v = __ldcg(src);
                while (v.y < need || v.w < need) { __nanosleep(32); v = __ldcg(src); }
            }
            ((float2*)hs[p])[tid] = make_float2(__uint_as_float(v.x), __uint_as_float(v.z));
        }
        __syncthreads();   // hs[p] ready (double buffer makes this the only BAR)
        float a0 = 0.f, a1 = 0.f, a2 = 0.f, a3 = 0.f;
#pragma unroll
        for (int k = 0; k < 16; k++) {
            float h = hs[p][lane + 32 * k];
            a0 = fmaf(wreg[0][k], h, a0);
            a1 = fmaf(wreg[1][k], h, a1);
            a2 = fmaf(wreg[2][k], h, a2);
            a3 = fmaf(wreg[3][k], h, a3);
        }
#pragma unroll
        for (int off = 16; off; off >>= 1) {
            a0 += __shfl_xor_sync(0xffffffffu, a0, off);
            a1 += __shfl_xor_sync(0xffffffffu, a1, off);
            a2 += __shfl_xor_sync(0xffffffffu, a2, off);
            a3 += __shfl_xor_sync(0xffffffffu, a3, off);
        }
        const float g0 = __shfl_sync(0xffffffffu, gval, 0);
        const float g1 = __shfl_sync(0xffffffffu, gval, 1);
        const float g2 = __shfl_sync(0xffffffffu, gval, 2);
        const float g3 = __shfl_sync(0xffffffffu, gval, 3);
        if (lane == 0) {
            float ig = fsig(a0 + g0);
            float fg = fsig(a1 + g1);
            float gg = ftanh(a2 + g2);
            float og = fsig(a3 + g3);
            c = fg * c + ig * gg;
            float h = og * ftanh(c);
            // packed store FIRST (critical path for peers), dense second
            unsigned long long pk = ((unsigned long long)(base + (unsigned)t + 1u) << 32)
                                    | (unsigned long long)__float_as_uint(h);
            __stcg(g_hp + (size_t)t_idx * 1024 + dir * HID + j, pk);
            __stcg(hout + (size_t)t_idx * 1024 + dir * HID + j, h);
        }
    }
}

// ---------------- final linear: feats[t,j] = h1[t]·lin_w[j] + lin_b[j] -----------
__global__ __launch_bounds__(512) void feats_k(const float* __restrict__ lin_w,
    const float* __restrict__ lin_b)
{
    __shared__ float hsm[1024];
    int t = blockIdx.x;
    for (int i = threadIdx.x; i < 1024; i += 512) hsm[i] = g_h1[(size_t)t * 1024 + i];
    __syncthreads();
    int w = threadIdx.x >> 5, lane = threadIdx.x & 31;
    for (int j = w; j < KTAGS; j += 16) {
        float s = 0.f;
        const float* wrow = lin_w + (size_t)j * 1024;
        for (int k = lane; k < 1024; k += 32) s += wrow[k] * hsm[k];
#pragma unroll
        for (int off = 16; off; off >>= 1) s += __shfl_xor_sync(0xffffffffu, s, off);
        if (lane == 0) g_feats[(size_t)t * KTAGS + j] = s + lin_b[j];
    }
}

// ---------------- CRF: 384 threads, j = tid>>3 (0..47), sub = tid&7 --------------
__global__ __launch_bounds__(384) void crf_k(const float* __restrict__ trans,
    const int* __restrict__ tags, const int* __restrict__ seqlen, float* __restrict__ out)
{
    __shared__ float alpha[2][KTAGS];
    __shared__ float scRed[384];
    const int tid = threadIdx.x;
    const int j = tid >> 3;
    const int sub = tid & 7;

    float tw[6];
#pragma unroll
    for (int kk = 0; kk < 6; kk++) tw[kk] = __ldg(trans + j * 48 + sub * 6 + kk);

    float sc = 0.f;
    for (int t = tid; t < TT; t += 384) {
        int cur = tags[t];
        int prev = t ? tags[t - 1] : START_TAG;
        sc += __ldg(trans + cur * 48 + prev) + g_feats[(size_t)t * KTAGS + cur];
    }
    scRed[tid] = sc;
    if (tid < KTAGS) alpha[0][tid] = (tid == START_TAG) ? 0.f : NEGV;
    __syncthreads();

    int p = 0;
    for (int t = 0; t < TT; t++) {
        float gf = __ldg(g_feats + (size_t)t * KTAGS + j);
        float a[6];
#pragma unroll
        for (int kk = 0; kk < 6; kk++) a[kk] = alpha[p][sub * 6 + kk] + tw[kk];
        float m = a[0];
#pragma unroll
        for (int kk = 1; kk < 6; kk++) m = fmaxf(m, a[kk]);
#pragma unroll
        for (int off = 1; off < 8; off <<= 1) m = fmaxf(m, __shfl_xor_sync(0xffffffffu, m, off));
        float s = 0.f;
#pragma unroll
        for (int kk = 0; kk < 6; kk++) s += __expf(a[kk] - m);
#pragma unroll
        for (int off = 1; off < 8; off <<= 1) s += __shfl_xor_sync(0xffffffffu, s, off);
        if (sub == 0) alpha[p ^ 1][j] = m + __logf(s) + gf;
        __syncthreads();
        p ^= 1;
    }

    if (tid == 0) {
        float score = 0.f;
        for (int k = 0; k < 384; k++) score += scRed[k];
        score += trans[END_TAG * 48 + tags[TT - 1]];
        float mm = -3.0e38f;
        for (int k = 0; k < KTAGS; k++) mm = fmaxf(mm, alpha[p][k] + trans[END_TAG * 48 + k]);
        float ss = 0.f;
        for (int k = 0; k < KTAGS; k++) ss += __expf(alpha[p][k] + trans[END_TAG * 48 + k] - mm);
        float logz = mm + __logf(ss);
        out[0] = (logz - score) / (float)seqlen[0];
    }
}

// ---------------- launch sequence ------------------------------------------------
// Order chosen so ncu (-s 5 -c 1) captures scan_k (launch index 5).
extern "C" void kernel_launch(void* const* d_in, const int* in_sizes, int n_in,
                              void* d_out, int out_size)
{
    (void)in_sizes; (void)n_in; (void)out_size;
    const int* tokens = (const int*)d_in[0];
    const int* tags   = (const int*)d_in[1];
    const int* seqlen = (const int*)d_in[2];
    const float* embed = (const float*)d_in[3];
    const float* w_ih_l0_f = (const float*)d_in[4];
    const float* w_hh_l0_f = (const float*)d_in[5];
    const float* b_ih_l0_f = (const float*)d_in[6];
    const float* b_hh_l0_f = (const float*)d_in[7];
    const float* w_ih_l0_b = (const float*)d_in[8];
    const float* w_hh_l0_b = (const float*)d_in[9];
    const float* b_ih_l0_b = (const float*)d_in[10];
    const float* b_hh_l0_b = (const float*)d_in[11];
    const float* w_ih_l1_f = (const float*)d_in[12];
    const float* w_hh_l1_f = (const float*)d_in[13];
    const float* b_ih_l1_f = (const float*)d_in[14];
    const float* b_hh_l1_f = (const float*)d_in[15];
    const float* w_ih_l1_b = (const float*)d_in[16];
    const float* w_hh_l1_b = (const float*)d_in[17];
    const float* b_ih_l1_b = (const float*)d_in[18];
    const float* b_hh_l1_b = (const float*)d_in[19];
    const float* lin_w = (const float*)d_in[20];
    const float* lin_b = (const float*)d_in[21];
    const float* trans = (const float*)d_in[22];
    float* out = (float*)d_out;

    clear_k<<<4096, 256>>>();                                       // 0 (zero g_hp tags)
    embed_k<<<TT, 64>>>(tokens, embed);                             // 1
    dim3 gg(GATES / 128, TT / 128);
    gemm_k<<<gg, 256>>>(0, w_ih_l0_f, b_ih_l0_f, b_hh_l0_f, 0, EMB);// 2
    gemm_k<<<gg, 256>>>(0, w_ih_l0_b, b_ih_l0_b, b_hh_l0_b, 1, EMB);// 3
    dummy_k<<<1, 32>>>();                                           // 4 (ncu filler)
    scan_k<<<2 * NSCAN, 256>>>(w_hh_l0_f, w_hh_l0_b, 0, 0u);        // 5 <- profiled
    gemm_k<<<gg, 256>>>(1, w_ih_l1_f, b_ih_l1_f, b_hh_l1_f, 0, 1024);
    gemm_k<<<gg, 256>>>(1, w_ih_l1_b, b_ih_l1_b, b_hh_l1_b, 1, 1024);
    scan_k<<<2 * NSCAN, 256>>>(w_hh_l1_f, w_hh_l1_b, 1, (unsigned)TT);
    feats_k<<<TT, 512>>>(lin_w, lin_b);
    crf_k<<<1, 384>>>(trans, tags, seqlen, out);
}